// round 13
// baseline (speedup 1.0000x reference)
#include <cuda_runtime.h>
#include <cuda_bf16.h>
#include <cstdint>

#define N_NODES 50000
#define E_EDGES 1600000
#define M_TOTAL (E_EDGES + N_NODES)
#define NT32 ((M_TOTAL + 31) / 32)     // 51563 pair-units
#define EU32 (E_EDGES / 32)            // 50000 exact: units >= this are self-loops
#define GRID_MSG 304

__device__ float g_agg[N_NODES * 64];
__device__ float g_YS[N_NODES * 64];   // x@W1[:32] + b1 + pos@W1[32:35]
__device__ float g_P[N_NODES * 64];    // pos@W1[32:35]
__device__ int g_ei_is64;
__device__ int g_tile;

// ---------------------------------------------------------------------------
__device__ __forceinline__ uint32_t smem_u32(const void* p) {
    uint32_t a;
    asm("{ .reg .u64 t; cvta.to.shared.u64 t, %1; cvt.u32.u64 %0, t; }" : "=r"(a) : "l"(p));
    return a;
}
__device__ __forceinline__ void ldsm4(uint32_t* r, uint32_t addr) {
    asm volatile("ldmatrix.sync.aligned.m8n8.x4.shared.b16 {%0,%1,%2,%3}, [%4];"
        : "=r"(r[0]), "=r"(r[1]), "=r"(r[2]), "=r"(r[3]) : "r"(addr));
}
__device__ __forceinline__ void mma_bf16(float* c, const uint32_t* a, uint32_t b0, uint32_t b1) {
    asm volatile("mma.sync.aligned.m16n8k16.row.col.f32.bf16.bf16.f32 "
        "{%0,%1,%2,%3}, {%4,%5,%6,%7}, {%8,%9}, {%0,%1,%2,%3};"
        : "+f"(c[0]), "+f"(c[1]), "+f"(c[2]), "+f"(c[3])
        : "r"(a[0]), "r"(a[1]), "r"(a[2]), "r"(a[3]), "r"(b0), "r"(b1));
}
__device__ __forceinline__ void split2(float a, float b, uint32_t& hi, uint32_t& lo) {
    __nv_bfloat162 h = __floats2bfloat162_rn(a, b);
    float ra = a - __bfloat162float(h.x);
    float rb = b - __bfloat162float(h.y);
    __nv_bfloat162 l = __floats2bfloat162_rn(ra, rb);
    hi = *(uint32_t*)&h; lo = *(uint32_t*)&l;
}
#define PAIR_BAR(id) asm volatile("bar.sync %0, 64;" :: "r"(id) : "memory")

// ---------------------------------------------------------------------------
__global__ void k_detect(const int* __restrict__ ei_raw) {
    __shared__ int any_nonzero;
    if (threadIdx.x == 0) any_nonzero = 0;
    __syncthreads();
    int w = ei_raw[2 * threadIdx.x + 1];
    if (w != 0) atomicOr(&any_nonzero, 1);
    __syncthreads();
    if (threadIdx.x == 0) g_ei_is64 = any_nonzero ? 0 : 1;
}

__global__ void k_zero() {
    int i = blockIdx.x * blockDim.x + threadIdx.x;
    if (i == 0) g_tile = 0;
    if (i < N_NODES * 64 / 4)
        ((float4*)g_agg)[i] = make_float4(0.f, 0.f, 0.f, 0.f);
}

// ---------------------------------------------------------------------------
// k_pre: per node, fp32-exact:
//   Y1 = x @ W1[:32] + b1 ; P = pos @ W1[32:35] ; YS = Y1 + P
// ---------------------------------------------------------------------------
#define SPX 0
#define SPW (64 * 36)
#define SPT (SPW + 32 * 64)
#define SMEM_PRE_BYTES ((SPT + 192) * 4)

__global__ __launch_bounds__(128) void k_pre(
    const float* __restrict__ x, const float* __restrict__ pos,
    const float* __restrict__ W1, const float* __restrict__ b1)
{
    extern __shared__ float sm[];
    float* sX = sm + SPX;
    float* sW = sm + SPW;
    float* sWT = sm + SPT;
    const int tid = threadIdx.x;
    const int nbase = blockIdx.x * 64;

    for (int i = tid; i < 32 * 16; i += 128)
        ((float4*)sW)[i] = __ldg((const float4*)W1 + i);
    if (tid < 64) {
        sWT[tid]       = W1[32 * 64 + tid];
        sWT[64 + tid]  = W1[33 * 64 + tid];
        sWT[128 + tid] = W1[34 * 64 + tid];
    }
    for (int idx = tid; idx < 64 * 8; idx += 128) {
        int r = idx >> 3, c4 = idx & 7;
        float4 v = make_float4(0.f, 0.f, 0.f, 0.f);
        if (nbase + r < N_NODES)
            v = *(const float4*)(x + (size_t)(nbase + r) * 32 + c4 * 4);
        *(float4*)(sX + r * 36 + c4 * 4) = v;
    }
    __syncthreads();

    const int tx = tid & 7, ty = tid >> 3;
    const int fbase = tx * 8;
    float acc[4][8];
    float bj[8];
    #pragma unroll
    for (int j = 0; j < 8; j++) bj[j] = __ldg(&b1[fbase + j]);
    #pragma unroll
    for (int i = 0; i < 4; i++)
        #pragma unroll
        for (int j = 0; j < 8; j++) acc[i][j] = bj[j];

    for (int k4 = 0; k4 < 8; k4++) {
        const int k0 = k4 * 4;
        float4 wv[4][2];
        #pragma unroll
        for (int kk = 0; kk < 4; kk++) {
            wv[kk][0] = *(const float4*)(sW + (k0 + kk) * 64 + fbase);
            wv[kk][1] = *(const float4*)(sW + (k0 + kk) * 64 + fbase + 4);
        }
        #pragma unroll
        for (int i = 0; i < 4; i++) {
            float4 av = *(const float4*)(sX + (ty + 16 * i) * 36 + k0);
            float a4[4] = {av.x, av.y, av.z, av.w};
            #pragma unroll
            for (int kk = 0; kk < 4; kk++) {
                const float* w = &wv[kk][0].x;
                #pragma unroll
                for (int j = 0; j < 8; j++)
                    acc[i][j] = fmaf(a4[kk], w[j], acc[i][j]);
            }
        }
    }
    #pragma unroll
    for (int i = 0; i < 4; i++) {
        int n = nbase + ty + 16 * i;
        if (n < N_NODES) {
            float p0 = pos[n * 3 + 0], p1 = pos[n * 3 + 1], p2 = pos[n * 3 + 2];
            float pv[8], ys[8];
            #pragma unroll
            for (int j = 0; j < 8; j++) {
                int c = fbase + j;
                pv[j] = fmaf(p0, sWT[c], fmaf(p1, sWT[64 + c], p2 * sWT[128 + c]));
                ys[j] = acc[i][j] + pv[j];
            }
            *(float4*)(g_YS + (size_t)n * 64 + fbase)     = make_float4(ys[0], ys[1], ys[2], ys[3]);
            *(float4*)(g_YS + (size_t)n * 64 + fbase + 4) = make_float4(ys[4], ys[5], ys[6], ys[7]);
            *(float4*)(g_P  + (size_t)n * 64 + fbase)     = make_float4(pv[0], pv[1], pv[2], pv[3]);
            *(float4*)(g_P  + (size_t)n * 64 + fbase + 4) = make_float4(pv[4], pv[5], pv[6], pv[7]);
        }
    }
}

// ---------------------------------------------------------------------------
// k_msg: warp-PAIR autonomous. Pair shares one 32-msg H1 tile; each warp owns
// a 32-col N-half with B-hi fragments HOISTED in registers for the whole
// kernel (B-lo stays in smem). Pair-scoped named barriers only.
// ---------------------------------------------------------------------------
#define O_W2_HI  0                      // 64 rows x 144 B
#define O_W2_LO  9216
#define O_B2     18432                  // 64 fp32
#define O_H1     18688                  // 4 pairs x 9216 (HI 4608 | LO 4608); 32 rows x 144B
#define O_SOUT   (O_H1 + 4 * 9216)     // 55552; 4 pairs x 8448 (32 rows x 66 fp32)
#define O_DSTP   (O_SOUT + 4 * 8448)   // 89344; 4 pairs x 128 B
#define O_U      (O_DSTP + 512)        // 89856; 4 pairs x 16 B
#define SMEM_MSG_BYTES (O_U + 64)      // 89920

__global__ __launch_bounds__(256, 2) void k_msg(
    const void* __restrict__ ei_raw,
    const float* __restrict__ W2, const float* __restrict__ bias2)
{
    extern __shared__ char smc[];
    const uint32_t smb = smem_u32(smc);
    uint32_t* W2_HI = (uint32_t*)(smc + O_W2_HI);
    uint32_t* W2_LO = (uint32_t*)(smc + O_W2_LO);
    float* sB2 = (float*)(smc + O_B2);

    const int tid = threadIdx.x;
    const int wid = tid >> 5;
    const int lid = tid & 31;

    // ---- stage W2^T split + b2 (once per CTA) ----
    for (int i = tid; i < 64 * 32; i += 256) {
        int n = i / 32, w = i % 32, k = 2 * w;
        uint32_t hi, lo; split2(W2[k * 64 + n], W2[(k + 1) * 64 + n], hi, lo);
        W2_HI[n * 36 + w] = hi; W2_LO[n * 36 + w] = lo;
    }
    if (tid < 64) sB2[tid] = bias2[tid];
    const int is64 = g_ei_is64;
    __syncthreads();   // last block barrier

    const int pair = wid >> 1;
    const int wp   = wid & 1;            // warp-in-pair: owns cols [wp*32, wp*32+32)
    const int barid = 1 + pair;

    const uint32_t h1a = smb + O_H1 + pair * 9216;             // HI base; LO +4608
    float* sOutP = (float*)(smc + O_SOUT + pair * 8448);
    int*   pairDst = (int*)(smc + O_DSTP + pair * 128);
    volatile int* sU = (volatile int*)(smc + O_U + pair * 16);

    // lane roles
    const int q    = lid & 15;           // index-load: message within warp's 16
    const int half = lid >> 4;           // 0 = src, 1 = dst
    const int gb_m = lid >> 4;           // gather: msg within pair-of-2
    const int gb_h = (lid >> 3) & 1;     //         half-row
    const int gb_s = lid & 7;            //         16B segment
    const int arow  = lid & 15;
    const int akoff = (lid >> 4) * 8;
    const int bnrow = (lid & 7) + ((lid & 16) ? 8 : 0);
    const int bk = ((lid >> 3) & 1) * 8;
    const int cq = lid & 3;

    // ---- hoist B-hi fragments for this warp's N-half (loop-invariant) ----
    uint32_t bhiR[4][2][4];
    #pragma unroll
    for (int kc = 0; kc < 4; kc++)
        #pragma unroll
        for (int g2 = 0; g2 < 2; g2++)
            ldsm4(bhiR[kc][g2],
                  smb + O_W2_HI + (wp * 32 + g2 * 16 + bnrow) * 144 + (kc * 16 + bk) * 2);

    for (;;) {
        if (wp == 0 && lid == 0) sU[0] = atomicAdd(&g_tile, 1);
        PAIR_BAR(barid);    // publishes u; also: prev unit fully consumed by both warps
        const int u = sU[0];
        if (u >= NT32) break;

        // ---- index load: 16 msgs for this warp; lanes 0-15 src, 16-31 dst ----
        int idxv;
        {
            int m = u * 32 + wp * 16 + q;
            if (u < EU32) {
                if (is64) idxv = (int)((const long long*)ei_raw)[(size_t)half * E_EDGES + m];
                else      idxv = ((const int*)ei_raw)[(size_t)half * E_EDGES + m];
                if ((unsigned)idxv >= N_NODES) idxv = 0;
                if (half) pairDst[wp * 16 + q] = idxv;
            } else {
                int mm = m - E_EDGES;
                int valid = mm < N_NODES;
                idxv = valid ? mm : 0;
                if (half) pairDst[wp * 16 + q] = valid ? mm : -1;
            }
        }

        // ---- gather: 16 rows at (wp*16 + j): relu(YS[src]-P[dst]) -> split ----
        #pragma unroll
        for (int it = 0; it < 8; it++) {
            int j = it * 2 + gb_m;
            int src = __shfl_sync(0xffffffffu, idxv, j);
            int dst = __shfl_sync(0xffffffffu, idxv, 16 + j);
            int n0 = gb_h * 32 + gb_s * 4;
            float4 ys = __ldg((const float4*)(g_YS + (size_t)src * 64 + n0));
            float4 pp = __ldg((const float4*)(g_P  + (size_t)dst * 64 + n0));
            float v0 = fmaxf(ys.x - pp.x, 0.f);
            float v1 = fmaxf(ys.y - pp.y, 0.f);
            float v2 = fmaxf(ys.z - pp.z, 0.f);
            float v3 = fmaxf(ys.w - pp.w, 0.f);
            uint32_t a, b, c, d;
            split2(v0, v1, a, b);
            split2(v2, v3, c, d);
            uint32_t off = (uint32_t)((wp * 16 + j) * 144 + gb_h * 64 + gb_s * 8);
            *(uint2*)(smc + (h1a - smb) + off)        = make_uint2(a, c);
            *(uint2*)(smc + (h1a - smb) + 4608 + off) = make_uint2(b, d);
        }
        PAIR_BAR(barid);    // H1 tile + pairDst complete

        // ---- GEMM: 32 msgs x this warp's 32 cols, K=64, bf16 3-pass ----
        float acc[2][4][4];
        #pragma unroll
        for (int mt = 0; mt < 2; mt++)
            #pragma unroll
            for (int nt = 0; nt < 4; nt++) {
                int c = wp * 32 + nt * 8 + 2 * cq;
                acc[mt][nt][0] = sB2[c]; acc[mt][nt][1] = sB2[c + 1];
                acc[mt][nt][2] = sB2[c]; acc[mt][nt][3] = sB2[c + 1];
            }
        #pragma unroll
        for (int kc = 0; kc < 4; kc++) {
            const int k0 = kc * 16;
            uint32_t ahi[2][4], alo[2][4];
            #pragma unroll
            for (int mt = 0; mt < 2; mt++) {
                uint32_t aaddr = h1a + (mt * 16 + arow) * 144 + (k0 + akoff) * 2;
                ldsm4(ahi[mt], aaddr);
                ldsm4(alo[mt], aaddr + 4608);
            }
            #pragma unroll
            for (int g2 = 0; g2 < 2; g2++) {
                uint32_t blo[4];
                ldsm4(blo, smb + O_W2_LO + (wp * 32 + g2 * 16 + bnrow) * 144 + (k0 + bk) * 2);
                #pragma unroll
                for (int mt = 0; mt < 2; mt++)
                    #pragma unroll
                    for (int t = 0; t < 2; t++) {
                        int nt = g2 * 2 + t;
                        mma_bf16(acc[mt][nt], ahi[mt], bhiR[kc][g2][2 * t], bhiR[kc][g2][2 * t + 1]);
                        mma_bf16(acc[mt][nt], alo[mt], bhiR[kc][g2][2 * t], bhiR[kc][g2][2 * t + 1]);
                        mma_bf16(acc[mt][nt], ahi[mt], blo[2 * t], blo[2 * t + 1]);
                    }
            }
        }

        // ---- epilogue: relu -> own cols of pair sOut (warp-private) ----
        {
            int rA = lid >> 2;
            #pragma unroll
            for (int mt = 0; mt < 2; mt++)
                #pragma unroll
                for (int nt = 0; nt < 4; nt++) {
                    int c = wp * 32 + nt * 8 + 2 * cq;
                    int r0 = mt * 16 + rA;
                    *(float2*)(sOutP + r0 * 66 + c) =
                        make_float2(fmaxf(acc[mt][nt][0], 0.f), fmaxf(acc[mt][nt][1], 0.f));
                    *(float2*)(sOutP + (r0 + 8) * 66 + c) =
                        make_float2(fmaxf(acc[mt][nt][2], 0.f), fmaxf(acc[mt][nt][3], 0.f));
                }
        }
        __syncwarp();

        // ---- coalesced predicated max scatter: 1 REDG line per msg per warp ----
        #pragma unroll 4
        for (int j = 0; j < 32; j++) {
            int dst = pairDst[j];
            if (dst < 0) continue;
            float v = sOutP[j * 66 + wp * 32 + lid];
            if (v > 0.f)
                atomicMax((int*)g_agg + (size_t)dst * 64 + wp * 32 + lid, __float_as_int(v));
        }
        // loop-top PAIR_BAR orders all reads before next unit's overwrites
    }
}

// ---------------------------------------------------------------------------
// k_out: out = agg @ Wg + bg    [50000,64] x [64,128]
// ---------------------------------------------------------------------------
#define SMO_A 0
#define SMO_W (64 * 68)
#define SMEM_OUT_BYTES ((64 * 68 + 64 * 128) * 4)

__global__ __launch_bounds__(128) void k_out(
    const float* __restrict__ Wg, const float* __restrict__ bg,
    float* __restrict__ out)
{
    extern __shared__ float sm[];
    float* sA = sm + SMO_A;
    float* sW = sm + SMO_W;
    const int tid = threadIdx.x;
    const int nbase = blockIdx.x * 64;

    {
        float4* dst4 = (float4*)sW;
        const float4* src4 = (const float4*)Wg;
        for (int i = tid; i < 64 * 32; i += 128) dst4[i] = __ldg(src4 + i);
    }
    for (int idx = tid; idx < 64 * 16; idx += 128) {
        int rr = idx >> 4, c4 = idx & 15;
        float4 v = make_float4(0.f, 0.f, 0.f, 0.f);
        if (nbase + rr < N_NODES)
            v = *(const float4*)(g_agg + (size_t)(nbase + rr) * 64 + c4 * 4);
        *(float4*)(sA + rr * 68 + c4 * 4) = v;
    }
    __syncthreads();

    const int tx = tid & 15;
    const int ty = tid >> 4;
    const int fbase = tx * 8;

    float acc[8][8];
    float bj[8];
    #pragma unroll
    for (int j = 0; j < 8; j++) bj[j] = __ldg(&bg[fbase + j]);
    #pragma unroll
    for (int i = 0; i < 8; i++)
        #pragma unroll
        for (int j = 0; j < 8; j++) acc[i][j] = bj[j];

    for (int k4 = 0; k4 < 16; k4++) {
        const int k0 = k4 * 4;
        float4 wv[4][2];
        #pragma unroll
        for (int kk = 0; kk < 4; kk++) {
            wv[kk][0] = *(const float4*)(sW + (k0 + kk) * 128 + fbase);
            wv[kk][1] = *(const float4*)(sW + (k0 + kk) * 128 + fbase + 4);
        }
        #pragma unroll
        for (int i = 0; i < 8; i++) {
            float4 av = *(const float4*)(sA + (ty + 8 * i) * 68 + k0);
            float a4[4] = {av.x, av.y, av.z, av.w};
            #pragma unroll
            for (int kk = 0; kk < 4; kk++) {
                const float* w = &wv[kk][0].x;
                #pragma unroll
                for (int j = 0; j < 8; j++)
                    acc[i][j] = fmaf(a4[kk], w[j], acc[i][j]);
            }
        }
    }

    #pragma unroll
    for (int i = 0; i < 8; i++) {
        int n = nbase + ty + 8 * i;
        if (n < N_NODES) {
            float4 v0, v1;
            v0.x = acc[i][0]; v0.y = acc[i][1]; v0.z = acc[i][2]; v0.w = acc[i][3];
            v1.x = acc[i][4]; v1.y = acc[i][5]; v1.z = acc[i][6]; v1.w = acc[i][7];
            *(float4*)(out + (size_t)n * 128 + fbase)     = v0;
            *(float4*)(out + (size_t)n * 128 + fbase + 4) = v1;
        }
    }
}

// ---------------------------------------------------------------------------
extern "C" void kernel_launch(void* const* d_in, const int* in_sizes, int n_in,
                              void* d_out, int out_size) {
    const float* x   = (const float*)d_in[0];
    const float* pos = (const float*)d_in[1];
    const void*  ei  = d_in[2];
    const float* W1  = (const float*)d_in[3];
    const float* b1  = (const float*)d_in[4];
    const float* W2  = (const float*)d_in[5];
    const float* b2  = (const float*)d_in[6];
    const float* Wg  = (const float*)d_in[7];
    const float* bg  = (const float*)d_in[8];
    float* out = (float*)d_out;

    cudaFuncSetAttribute(k_msg, cudaFuncAttributeMaxDynamicSharedMemorySize, SMEM_MSG_BYTES);
    cudaFuncSetAttribute(k_out, cudaFuncAttributeMaxDynamicSharedMemorySize, SMEM_OUT_BYTES);
    cudaFuncSetAttribute(k_pre, cudaFuncAttributeMaxDynamicSharedMemorySize, SMEM_PRE_BYTES);

    k_detect<<<1, 1024>>>((const int*)ei);
    k_zero<<<(N_NODES * 64 / 4 + 255) / 256, 256>>>();
    k_pre<<<(N_NODES + 63) / 64, 128, SMEM_PRE_BYTES>>>(x, pos, W1, b1);
    k_msg<<<GRID_MSG, 256, SMEM_MSG_BYTES>>>(ei, W2, b2);
    k_out<<<(N_NODES + 63) / 64, 128, SMEM_OUT_BYTES>>>(Wg, bg, out);
}

// round 14
// speedup vs baseline: 1.1704x; 1.1704x over previous
#include <cuda_runtime.h>
#include <cuda_bf16.h>
#include <cstdint>

#define N_NODES 50000
#define E_EDGES 1600000
#define M_TOTAL (E_EDGES + N_NODES)
#define NT32 ((M_TOTAL + 31) / 32)     // 51563 warp-units of 32 msgs
#define EU32 (E_EDGES / 32)            // 50000 exact: units >= this are self-loops
#define GRID_MSG 304

__device__ float g_agg[N_NODES * 64];
__device__ float g_YS[N_NODES * 64];   // x@W1[:32] + b1 + pos@W1[32:35]
__device__ float g_P[N_NODES * 64];    // pos@W1[32:35]
__device__ int g_ei_is64;
__device__ int g_tile;

// ---------------------------------------------------------------------------
__device__ __forceinline__ uint32_t smem_u32(const void* p) {
    uint32_t a;
    asm("{ .reg .u64 t; cvta.to.shared.u64 t, %1; cvt.u32.u64 %0, t; }" : "=r"(a) : "l"(p));
    return a;
}
__device__ __forceinline__ void ldsm4(uint32_t* r, uint32_t addr) {
    asm volatile("ldmatrix.sync.aligned.m8n8.x4.shared.b16 {%0,%1,%2,%3}, [%4];"
        : "=r"(r[0]), "=r"(r[1]), "=r"(r[2]), "=r"(r[3]) : "r"(addr));
}
__device__ __forceinline__ void mma_bf16(float* c, const uint32_t* a, uint32_t b0, uint32_t b1) {
    asm volatile("mma.sync.aligned.m16n8k16.row.col.f32.bf16.bf16.f32 "
        "{%0,%1,%2,%3}, {%4,%5,%6,%7}, {%8,%9}, {%0,%1,%2,%3};"
        : "+f"(c[0]), "+f"(c[1]), "+f"(c[2]), "+f"(c[3])
        : "r"(a[0]), "r"(a[1]), "r"(a[2]), "r"(a[3]), "r"(b0), "r"(b1));
}
__device__ __forceinline__ void split2(float a, float b, uint32_t& hi, uint32_t& lo) {
    __nv_bfloat162 h = __floats2bfloat162_rn(a, b);
    float ra = a - __bfloat162float(h.x);
    float rb = b - __bfloat162float(h.y);
    __nv_bfloat162 l = __floats2bfloat162_rn(ra, rb);
    hi = *(uint32_t*)&h; lo = *(uint32_t*)&l;
}

// ---------------------------------------------------------------------------
__global__ void k_detect(const int* __restrict__ ei_raw) {
    __shared__ int any_nonzero;
    if (threadIdx.x == 0) any_nonzero = 0;
    __syncthreads();
    int w = ei_raw[2 * threadIdx.x + 1];
    if (w != 0) atomicOr(&any_nonzero, 1);
    __syncthreads();
    if (threadIdx.x == 0) g_ei_is64 = any_nonzero ? 0 : 1;
}

__global__ void k_zero() {
    int i = blockIdx.x * blockDim.x + threadIdx.x;
    if (i == 0) g_tile = 0;
    if (i < N_NODES * 64 / 4)
        ((float4*)g_agg)[i] = make_float4(0.f, 0.f, 0.f, 0.f);
}

// ---------------------------------------------------------------------------
// k_pre: per node, fp32-exact:
//   Y1 = x @ W1[:32] + b1 ; P = pos @ W1[32:35] ; YS = Y1 + P
// ---------------------------------------------------------------------------
#define SPX 0
#define SPW (64 * 36)
#define SPT (SPW + 32 * 64)
#define SMEM_PRE_BYTES ((SPT + 192) * 4)

__global__ __launch_bounds__(128) void k_pre(
    const float* __restrict__ x, const float* __restrict__ pos,
    const float* __restrict__ W1, const float* __restrict__ b1)
{
    extern __shared__ float sm[];
    float* sX = sm + SPX;
    float* sW = sm + SPW;
    float* sWT = sm + SPT;
    const int tid = threadIdx.x;
    const int nbase = blockIdx.x * 64;

    for (int i = tid; i < 32 * 16; i += 128)
        ((float4*)sW)[i] = __ldg((const float4*)W1 + i);
    if (tid < 64) {
        sWT[tid]       = W1[32 * 64 + tid];
        sWT[64 + tid]  = W1[33 * 64 + tid];
        sWT[128 + tid] = W1[34 * 64 + tid];
    }
    for (int idx = tid; idx < 64 * 8; idx += 128) {
        int r = idx >> 3, c4 = idx & 7;
        float4 v = make_float4(0.f, 0.f, 0.f, 0.f);
        if (nbase + r < N_NODES)
            v = *(const float4*)(x + (size_t)(nbase + r) * 32 + c4 * 4);
        *(float4*)(sX + r * 36 + c4 * 4) = v;
    }
    __syncthreads();

    const int tx = tid & 7, ty = tid >> 3;
    const int fbase = tx * 8;
    float acc[4][8];
    float bj[8];
    #pragma unroll
    for (int j = 0; j < 8; j++) bj[j] = __ldg(&b1[fbase + j]);
    #pragma unroll
    for (int i = 0; i < 4; i++)
        #pragma unroll
        for (int j = 0; j < 8; j++) acc[i][j] = bj[j];

    for (int k4 = 0; k4 < 8; k4++) {
        const int k0 = k4 * 4;
        float4 wv[4][2];
        #pragma unroll
        for (int kk = 0; kk < 4; kk++) {
            wv[kk][0] = *(const float4*)(sW + (k0 + kk) * 64 + fbase);
            wv[kk][1] = *(const float4*)(sW + (k0 + kk) * 64 + fbase + 4);
        }
        #pragma unroll
        for (int i = 0; i < 4; i++) {
            float4 av = *(const float4*)(sX + (ty + 16 * i) * 36 + k0);
            float a4[4] = {av.x, av.y, av.z, av.w};
            #pragma unroll
            for (int kk = 0; kk < 4; kk++) {
                const float* w = &wv[kk][0].x;
                #pragma unroll
                for (int j = 0; j < 8; j++)
                    acc[i][j] = fmaf(a4[kk], w[j], acc[i][j]);
            }
        }
    }
    #pragma unroll
    for (int i = 0; i < 4; i++) {
        int n = nbase + ty + 16 * i;
        if (n < N_NODES) {
            float p0 = pos[n * 3 + 0], p1 = pos[n * 3 + 1], p2 = pos[n * 3 + 2];
            float pv[8], ys[8];
            #pragma unroll
            for (int j = 0; j < 8; j++) {
                int c = fbase + j;
                pv[j] = fmaf(p0, sWT[c], fmaf(p1, sWT[64 + c], p2 * sWT[128 + c]));
                ys[j] = acc[i][j] + pv[j];
            }
            *(float4*)(g_YS + (size_t)n * 64 + fbase)     = make_float4(ys[0], ys[1], ys[2], ys[3]);
            *(float4*)(g_YS + (size_t)n * 64 + fbase + 4) = make_float4(ys[4], ys[5], ys[6], ys[7]);
            *(float4*)(g_P  + (size_t)n * 64 + fbase)     = make_float4(pv[0], pv[1], pv[2], pv[3]);
            *(float4*)(g_P  + (size_t)n * 64 + fbase + 4) = make_float4(pv[4], pv[5], pv[6], pv[7]);
        }
    }
}

// ---------------------------------------------------------------------------
// k_msg: warp-autonomous, 32-msg units (2 m-tiles). B fragments amortized
// over 2 m-tiles; epilogue atomics issued DIRECTLY from mma accumulators
// (dst via shuffle) — no sOut smem roundtrip. Only __syncwarp ordering.
// ---------------------------------------------------------------------------
#define O_W2_HI  0                      // 64 rows x 144 B
#define O_W2_LO  9216
#define O_B2     18432                  // 64 fp32
#define O_H1     18688                  // 8 warps x 9216 (HI 4608 | LO 4608), 32 rows x 144B
#define SMEM_MSG_BYTES (18688 + 8 * 9216)   // 92416

__global__ __launch_bounds__(256, 2) void k_msg(
    const void* __restrict__ ei_raw,
    const float* __restrict__ W2, const float* __restrict__ bias2)
{
    extern __shared__ char smc[];
    const uint32_t smb = smem_u32(smc);
    uint32_t* W2_HI = (uint32_t*)(smc + O_W2_HI);
    uint32_t* W2_LO = (uint32_t*)(smc + O_W2_LO);
    float* sB2 = (float*)(smc + O_B2);

    const int tid = threadIdx.x;
    const int wid = tid >> 5;
    const int lid = tid & 31;

    // ---- stage W2^T split + b2 (once per CTA) ----
    for (int i = tid; i < 64 * 32; i += 256) {
        int n = i / 32, w = i % 32, k = 2 * w;
        uint32_t hi, lo; split2(W2[k * 64 + n], W2[(k + 1) * 64 + n], hi, lo);
        W2_HI[n * 36 + w] = hi; W2_LO[n * 36 + w] = lo;
    }
    if (tid < 64) sB2[tid] = bias2[tid];
    const int is64 = g_ei_is64;
    __syncthreads();   // last block barrier

    // warp-private H1 block: HI at h1w, LO at h1w + 4608
    const uint32_t h1w = smb + O_H1 + wid * 9216;

    // lane roles
    const int q    = lid & 15;           // index-load: message within 16
    const int half = lid >> 4;           // 0 = src, 1 = dst
    const int gb_m = lid >> 4;           // gather: msg within pair-of-2
    const int gb_h = (lid >> 3) & 1;     //         half-row
    const int gb_s = lid & 7;            //         16B segment
    const int arow  = lid & 15;
    const int akoff = (lid >> 4) * 8;
    const int bnrow = (lid & 7) + ((lid & 16) ? 8 : 0);
    const int bk = ((lid >> 3) & 1) * 8;
    const int cq = lid & 3;

    // hoisted bias pairs for this lane's columns (loop-invariant)
    float bb[8][2];
    #pragma unroll
    for (int nb = 0; nb < 8; nb++) {
        bb[nb][0] = sB2[8 * nb + 2 * cq];
        bb[nb][1] = sB2[8 * nb + 2 * cq + 1];
    }

    for (;;) {
        int u;
        if (lid == 0) u = atomicAdd(&g_tile, 1);
        u = __shfl_sync(0xffffffffu, u, 0);
        if (u >= NT32) break;

        // ---- index load: idx0 = msgs 0-15, idx1 = msgs 16-31 ----
        // lanes 0-15 hold src, 16-31 hold dst; -1 marks invalid (skip atomic)
        int idx0, idx1;
        if (u < EU32) {
            int m0 = u * 32 + q;
            int m1 = m0 + 16;
            if (is64) {
                idx0 = (int)((const long long*)ei_raw)[(size_t)half * E_EDGES + m0];
                idx1 = (int)((const long long*)ei_raw)[(size_t)half * E_EDGES + m1];
            } else {
                idx0 = ((const int*)ei_raw)[(size_t)half * E_EDGES + m0];
                idx1 = ((const int*)ei_raw)[(size_t)half * E_EDGES + m1];
            }
            if ((unsigned)idx0 >= N_NODES) idx0 = 0;
            if ((unsigned)idx1 >= N_NODES) idx1 = 0;
        } else {
            int mm0 = u * 32 + q - E_EDGES;
            int mm1 = mm0 + 16;
            idx0 = (mm0 < N_NODES) ? mm0 : -1;
            idx1 = (mm1 < N_NODES) ? mm1 : -1;
        }

        // ---- gather: 32 rows: relu(YS[src]-P[dst]) -> split -> H1 ----
        #pragma unroll
        for (int it = 0; it < 16; it++) {
            int j = it * 2 + gb_m;                  // row 0..31
            int iv = (j < 16) ? idx0 : idx1;
            int src = __shfl_sync(0xffffffffu, iv, j & 15);
            int dst = __shfl_sync(0xffffffffu, iv, 16 + (j & 15));
            int s = src < 0 ? 0 : src;
            int d = dst < 0 ? 0 : dst;
            int n0 = gb_h * 32 + gb_s * 4;
            float4 ys = __ldg((const float4*)(g_YS + (size_t)s * 64 + n0));
            float4 pp = __ldg((const float4*)(g_P  + (size_t)d * 64 + n0));
            float v0 = fmaxf(ys.x - pp.x, 0.f);
            float v1 = fmaxf(ys.y - pp.y, 0.f);
            float v2 = fmaxf(ys.z - pp.z, 0.f);
            float v3 = fmaxf(ys.w - pp.w, 0.f);
            uint32_t a, b, c, d2;
            split2(v0, v1, a, b);
            split2(v2, v3, c, d2);
            uint32_t off = (uint32_t)(j * 144 + gb_h * 64 + gb_s * 8);
            *(uint2*)(smc + (h1w - smb) + off)        = make_uint2(a, c);
            *(uint2*)(smc + (h1w - smb) + 4608 + off) = make_uint2(b, d2);
        }
        __syncwarp();

        // ---- GEMM: 32 msgs x 64 cols, K=64, bf16 3-pass ----
        float acc[2][8][4];
        #pragma unroll
        for (int mt = 0; mt < 2; mt++)
            #pragma unroll
            for (int nb = 0; nb < 8; nb++) {
                acc[mt][nb][0] = bb[nb][0]; acc[mt][nb][1] = bb[nb][1];
                acc[mt][nb][2] = bb[nb][0]; acc[mt][nb][3] = bb[nb][1];
            }
        #pragma unroll
        for (int kc = 0; kc < 4; kc++) {
            const int k0 = kc * 16;
            uint32_t ahi[2][4], alo[2][4];
            #pragma unroll
            for (int mt = 0; mt < 2; mt++) {
                uint32_t aaddr = h1w + (mt * 16 + arow) * 144 + (k0 + akoff) * 2;
                ldsm4(ahi[mt], aaddr);
                ldsm4(alo[mt], aaddr + 4608);
            }
            #pragma unroll
            for (int hf = 0; hf < 4; hf++) {
                uint32_t bhi[4], blo[4];
                uint32_t baddr = smb + O_W2_HI + (hf * 16 + bnrow) * 144 + (k0 + bk) * 2;
                ldsm4(bhi, baddr);
                ldsm4(blo, baddr + (O_W2_LO - O_W2_HI));
                #pragma unroll
                for (int mt = 0; mt < 2; mt++)
                    #pragma unroll
                    for (int t = 0; t < 2; t++) {
                        int nb = hf * 2 + t;
                        mma_bf16(acc[mt][nb], ahi[mt], bhi[2 * t], bhi[2 * t + 1]);
                        mma_bf16(acc[mt][nb], alo[mt], bhi[2 * t], bhi[2 * t + 1]);
                        mma_bf16(acc[mt][nb], ahi[mt], blo[2 * t], blo[2 * t + 1]);
                    }
            }
        }
        __syncwarp();   // H1 ldsm reads complete before next unit's gather

        // ---- epilogue: relu + atomicMax DIRECT from accumulators ----
        // lane holds rows (mt*16 + rA) and (+8), cols 8nb+2cq (+1)
        {
            int rA = lid >> 2;
            #pragma unroll
            for (int mt = 0; mt < 2; mt++) {
                int iv = mt ? idx1 : idx0;
                int dst0 = __shfl_sync(0xffffffffu, iv, 16 + rA);
                int dst1 = __shfl_sync(0xffffffffu, iv, 16 + rA + 8);
                #pragma unroll
                for (int nb = 0; nb < 8; nb++) {
                    int c = 8 * nb + 2 * cq;
                    float v0 = fmaxf(acc[mt][nb][0], 0.f);
                    float v1 = fmaxf(acc[mt][nb][1], 0.f);
                    float v2 = fmaxf(acc[mt][nb][2], 0.f);
                    float v3 = fmaxf(acc[mt][nb][3], 0.f);
                    if (dst0 >= 0) {
                        int* ap = (int*)g_agg + (size_t)dst0 * 64 + c;
                        if (v0 > 0.f) atomicMax(ap,     __float_as_int(v0));
                        if (v1 > 0.f) atomicMax(ap + 1, __float_as_int(v1));
                    }
                    if (dst1 >= 0) {
                        int* ap = (int*)g_agg + (size_t)dst1 * 64 + c;
                        if (v2 > 0.f) atomicMax(ap,     __float_as_int(v2));
                        if (v3 > 0.f) atomicMax(ap + 1, __float_as_int(v3));
                    }
                }
            }
        }
    }
}

// ---------------------------------------------------------------------------
// k_out: out = agg @ Wg + bg    [50000,64] x [64,128]
// ---------------------------------------------------------------------------
#define SMO_A 0
#define SMO_W (64 * 68)
#define SMEM_OUT_BYTES ((64 * 68 + 64 * 128) * 4)

__global__ __launch_bounds__(128) void k_out(
    const float* __restrict__ Wg, const float* __restrict__ bg,
    float* __restrict__ out)
{
    extern __shared__ float sm[];
    float* sA = sm + SMO_A;
    float* sW = sm + SMO_W;
    const int tid = threadIdx.x;
    const int nbase = blockIdx.x * 64;

    {
        float4* dst4 = (float4*)sW;
        const float4* src4 = (const float4*)Wg;
        for (int i = tid; i < 64 * 32; i += 128) dst4[i] = __ldg(src4 + i);
    }
    for (int idx = tid; idx < 64 * 16; idx += 128) {
        int rr = idx >> 4, c4 = idx & 15;
        float4 v = make_float4(0.f, 0.f, 0.f, 0.f);
        if (nbase + rr < N_NODES)
            v = *(const float4*)(g_agg + (size_t)(nbase + rr) * 64 + c4 * 4);
        *(float4*)(sA + rr * 68 + c4 * 4) = v;
    }
    __syncthreads();

    const int tx = tid & 15;
    const int ty = tid >> 4;
    const int fbase = tx * 8;

    float acc[8][8];
    float bj[8];
    #pragma unroll
    for (int j = 0; j < 8; j++) bj[j] = __ldg(&bg[fbase + j]);
    #pragma unroll
    for (int i = 0; i < 8; i++)
        #pragma unroll
        for (int j = 0; j < 8; j++) acc[i][j] = bj[j];

    for (int k4 = 0; k4 < 16; k4++) {
        const int k0 = k4 * 4;
        float4 wv[4][2];
        #pragma unroll
        for (int kk = 0; kk < 4; kk++) {
            wv[kk][0] = *(const float4*)(sW + (k0 + kk) * 128 + fbase);
            wv[kk][1] = *(const float4*)(sW + (k0 + kk) * 128 + fbase + 4);
        }
        #pragma unroll
        for (int i = 0; i < 8; i++) {
            float4 av = *(const float4*)(sA + (ty + 8 * i) * 68 + k0);
            float a4[4] = {av.x, av.y, av.z, av.w};
            #pragma unroll
            for (int kk = 0; kk < 4; kk++) {
                const float* w = &wv[kk][0].x;
                #pragma unroll
                for (int j = 0; j < 8; j++)
                    acc[i][j] = fmaf(a4[kk], w[j], acc[i][j]);
            }
        }
    }

    #pragma unroll
    for (int i = 0; i < 8; i++) {
        int n = nbase + ty + 8 * i;
        if (n < N_NODES) {
            float4 v0, v1;
            v0.x = acc[i][0]; v0.y = acc[i][1]; v0.z = acc[i][2]; v0.w = acc[i][3];
            v1.x = acc[i][4]; v1.y = acc[i][5]; v1.z = acc[i][6]; v1.w = acc[i][7];
            *(float4*)(out + (size_t)n * 128 + fbase)     = v0;
            *(float4*)(out + (size_t)n * 128 + fbase + 4) = v1;
        }
    }
}

// ---------------------------------------------------------------------------
extern "C" void kernel_launch(void* const* d_in, const int* in_sizes, int n_in,
                              void* d_out, int out_size) {
    const float* x   = (const float*)d_in[0];
    const float* pos = (const float*)d_in[1];
    const void*  ei  = d_in[2];
    const float* W1  = (const float*)d_in[3];
    const float* b1  = (const float*)d_in[4];
    const float* W2  = (const float*)d_in[5];
    const float* b2  = (const float*)d_in[6];
    const float* Wg  = (const float*)d_in[7];
    const float* bg  = (const float*)d_in[8];
    float* out = (float*)d_out;

    cudaFuncSetAttribute(k_msg, cudaFuncAttributeMaxDynamicSharedMemorySize, SMEM_MSG_BYTES);
    cudaFuncSetAttribute(k_out, cudaFuncAttributeMaxDynamicSharedMemorySize, SMEM_OUT_BYTES);
    cudaFuncSetAttribute(k_pre, cudaFuncAttributeMaxDynamicSharedMemorySize, SMEM_PRE_BYTES);

    k_detect<<<1, 1024>>>((const int*)ei);
    k_zero<<<(N_NODES * 64 / 4 + 255) / 256, 256>>>();
    k_pre<<<(N_NODES + 63) / 64, 128, SMEM_PRE_BYTES>>>(x, pos, W1, b1);
    k_msg<<<GRID_MSG, 256, SMEM_MSG_BYTES>>>(ei, W2, b2);
    k_out<<<(N_NODES + 63) / 64, 128, SMEM_OUT_BYTES>>>(Wg, bg, out);
}